// round 12
// baseline (speedup 1.0000x reference)
#include <cuda_runtime.h>
#include <cuda_bf16.h>

// ---------- static device scratch ----------
__device__ float g_Mt[1024 * 1024];
__device__ float g_mpart[8 * 1024];
__device__ float g_meanS[64 * 588];
__device__ float g_meanO[64 * 588];
__device__ float g_npool[64 * 9408];
__device__ float g_part[4718592];
__device__ float g_feats[64 * 3 * 1024];
__device__ float g_t[192 * 1024];
__device__ float g_wofc[1024];
__device__ float g_wvofc[1024];
__device__ float g_vproj[192];
__device__ float g_tokfc[192];

// ---------- helpers ----------
__device__ __forceinline__ unsigned long long pk2(float lo, float hi) {
    unsigned long long r;
    asm("mov.b64 %0,{%1,%2};" : "=l"(r) : "r"(__float_as_uint(lo)), "r"(__float_as_uint(hi)));
    return r;
}
__device__ __forceinline__ void fma2(unsigned long long& acc, unsigned long long a, unsigned long long b) {
    asm("fma.rn.f32x2 %0, %1, %2, %0;" : "+l"(acc) : "l"(a), "l"(b));
}
__device__ __forceinline__ void cp16(unsigned dst, const float* src) {
    asm volatile("cp.async.ca.shared.global [%0], [%1], 16;" :: "r"(dst), "l"(src));
}
__device__ __forceinline__ float blk_sum256(float v) {
    __shared__ float sb[8];
    int lane = threadIdx.x & 31, w = threadIdx.x >> 5;
    for (int o = 16; o; o >>= 1) v += __shfl_xor_sync(0xffffffffu, v, o);
    if (!lane) sb[w] = v;
    __syncthreads();
    float t = 0.f;
#pragma unroll
    for (int i = 0; i < 8; i++) t += sb[i];
    __syncthreads();
    return t;
}

// ---------- fused setup: DCT matrix + pos-emb partials + Wo@Wfc ----------
__global__ void __launch_bounds__(256) k_setup(const float* __restrict__ pos,
                                               const float* __restrict__ Wo,
                                               const float* __restrict__ Wfc) {
    int bx = blockIdx.x, tid = threadIdx.x;
    if (bx < 4096) {                               // DCT matrix, JAX fp32 arg rounding
        int idx = bx * 256 + tid;
        int d = idx >> 10, k = idx & 1023;
        float t1 = __fmul_rn(3.14159265358979323846f, (float)d + 0.5f);
        float t2 = __fmul_rn(t1, (float)k);
        float t3 = __fmul_rn(t2, 0.0009765625f);
        float q = rintf(t3 * 0.6366197723675814f);
        float r = __fmaf_rn(q, -1.57079637050628662109375f, t3);
        r = __fmaf_rn(q, 4.37113900018624283e-8f, r);
        int qi = ((int)q) & 3;
        float v = (qi & 1) ? sinf(r) : cosf(r);
        float c = (qi == 1 || qi == 2) ? -v : v;
        float s = (k == 0) ? 0.03125f : 0.044194173824159216f;
        g_Mt[idx] = c * s;
    } else if (bx < 4104) {                        // pos-emb partial sums (32 tokens each)
        int p = bx - 4096;
#pragma unroll
        for (int qq = 0; qq < 4; qq++) {
            int d = tid + qq * 256;
            float s = 0.f;
#pragma unroll 4
            for (int t = 0; t < 32; t++) s += pos[(p * 32 + t) * 1024 + d];
            g_mpart[p * 1024 + d] = s;
        }
    } else {                                       // wofc = Wo @ Wfc (2 warps per row)
        int bl = bx - 4104;
        int row = bl * 4 + (tid >> 6);
        int l64 = tid & 63;
        const float* wr = Wo + (size_t)row * 1024;
        float s = 0.f;
#pragma unroll 16
        for (int it = 0; it < 16; it++) s += wr[it * 64 + l64] * Wfc[it * 64 + l64];
        for (int o = 16; o; o >>= 1) s += __shfl_xor_sync(0xffffffffu, s, o);
        __shared__ float ss[8];
        if (!(tid & 31)) ss[tid >> 5] = s;
        __syncthreads();
        if (tid < 4) g_wofc[bl * 4 + tid] = ss[2 * tid] + ss[2 * tid + 1];
    }
}
__global__ void __launch_bounds__(256) k_wvofc(const float* __restrict__ Wv) {
    int row = blockIdx.x * 4 + (threadIdx.x >> 6), l64 = threadIdx.x & 63;
    const float* wr = Wv + (size_t)row * 1024;
    float s = 0.f;
#pragma unroll 16
    for (int it = 0; it < 16; it++) s += wr[it * 64 + l64] * g_wofc[it * 64 + l64];
    for (int o = 16; o; o >>= 1) s += __shfl_xor_sync(0xffffffffu, s, o);
    __shared__ float ss[8];
    if (!(threadIdx.x & 31)) ss[threadIdx.x >> 5] = s;
    __syncthreads();
    if (threadIdx.x < 4) g_wvofc[blockIdx.x * 4 + threadIdx.x] = ss[2 * threadIdx.x] + ss[2 * threadIdx.x + 1];
}

// ---------- fused per-plane: float4 load to smem, pools + orig bins + shuffled bins ----------
__global__ void __launch_bounds__(1024) k_planes(const float* __restrict__ x,
                                                 const int* __restrict__ sidx,
                                                 const int* __restrict__ rot,
                                                 const int* __restrict__ fh,
                                                 const int* __restrict__ fw) {
    extern __shared__ float sm[];
    float* pl = sm;                 // 224 rows x 228 stride (16B-aligned rows)
    float* p4 = sm + 228 * 224;     // 56x56
    int bc = blockIdx.x, b = bc / 3, c = bc % 3, tid = threadIdx.x;
    const float* plane = x + (size_t)bc * 50176;

    __shared__ int sm_m[49], sm_k[49], sm_h[49], sm_w[49];
    if (tid < 49) {
        sm_m[tid] = sidx[tid];
        sm_k[tid] = rot[b * 49 + tid];
        sm_h[tid] = fh[b * 49 + tid];
        sm_w[tid] = fw[b * 49 + tid];
    }
    for (int idx4 = tid; idx4 < 12544; idx4 += 1024) {      // 224*56 float4
        int i = idx4 / 56, j4 = idx4 - i * 56;
        *(float4*)(pl + i * 228 + j4 * 4) = *(const float4*)(plane + i * 224 + j4 * 4);
    }
    __syncthreads();
    for (int cell = tid; cell < 3136; cell += 1024) {
        int i = cell / 56, j = cell - (cell / 56) * 56;
        const float* p = pl + (i * 4) * 228 + j * 4;
        float s = 0.f;
#pragma unroll
        for (int r = 0; r < 4; r++)
            s += p[r * 228] + p[r * 228 + 1] + p[r * 228 + 2] + p[r * 228 + 3];
        p4[cell] = s;
    }
    __syncthreads();
    for (int cell = tid; cell < 3136; cell += 1024) {
        int i = cell / 56, j = cell - (cell / 56) * 56;
        int i0 = i & ~1, j0 = j & ~1;
        float s8 = p4[i0 * 56 + j0] + p4[i0 * 56 + j0 + 1] +
                   p4[(i0 + 1) * 56 + j0] + p4[(i0 + 1) * 56 + j0 + 1];
        g_npool[(size_t)bc * 3136 + cell] = p4[cell] * 0.0625f - s8 * 0.015625f;
    }
    if (tid < 196) {                               // original-branch bins
        int dy = tid / 14, dx = tid - (tid / 14) * 14;
        float s = 0.f;
        for (int ii = 0; ii < 16; ii++) {
            const float* row = pl + (ii * 14 + dy) * 228;
#pragma unroll
            for (int jj = 0; jj < 16; jj++) s += row[jj * 14 + dx];
        }
        g_meanO[b * 588 + c * 196 + tid] = s * (1.0f / 256.0f);
    } else if (tid >= 256 && tid < 452) {          // shuffled-branch bins (inverse map)
        int bin = tid - 256, dy = bin / 14, dx = bin - (bin / 14) * 14;
        float s = 0.f;
        for (int ii = 0; ii < 16; ii++) {
            int y = ii * 14 + dy;
            int pr = y >> 5, r = y & 31;
#pragma unroll 4
            for (int jj = 0; jj < 16; jj++) {
                int xx = jj * 14 + dx;
                int pc = xx >> 5, cc = xx & 31;
                int n = pr * 7 + pc;
                int m = sm_m[n];
                int c1 = sm_w[n] ? 31 - cc : cc;
                int r1 = sm_h[n] ? 31 - r : r;
                int k = sm_k[n], sr, sc;
                if (k == 0)      { sr = r1;      sc = c1;      }
                else if (k == 1) { sr = c1;      sc = 31 - r1; }
                else if (k == 2) { sr = 31 - r1; sc = 31 - c1; }
                else             { sr = 31 - c1; sc = r1;      }
                s += pl[((m / 7) * 32 + sr) * 228 + (m % 7) * 32 + sc];
            }
        }
        g_meanS[b * 588 + c * 196 + bin] = s * (1.0f / 256.0f);
    }
}

// ---------- GEMM body: 64 rows x 256 cols; cp.async W + reg-prefetch A, double buffer ----------
// REQUIREMENT: kbeg % 4 == 0. a_sm: 2*1088 floats, w_sm: 2*4096 floats.
__device__ __forceinline__ void gemm_body(const float* __restrict__ A, const float* __restrict__ W,
                                          float* __restrict__ po, int K, int kbeg, int kend,
                                          float* a_smb, float* w_smb) {
    int tid = threadIdx.x;
    int cq = tid & 63;
    int c0 = blockIdx.x * 256 + cq * 4;
    int row0 = (tid >> 6) * 16;
    int am = tid >> 2, ak = (tid & 3) * 4;      // A: row am, 4 k's from ak
    int wr = tid >> 4, wc = (tid & 15) * 16;    // W: row wr, 16 cols from wc
    int cbase = blockIdx.x * 256;
    unsigned w_base = (unsigned)__cvta_generic_to_shared(w_smb);

    unsigned long long acc[32];
#pragma unroll
    for (int i = 0; i < 32; i++) acc[i] = 0ULL;

    int ntiles = (kend - kbeg + 15) >> 4;
    float4 a4;

#define PREFW(t) do {                                                                  \
        int k0 = kbeg + (t) * 16;                                                      \
        int cb = kend - k0;                                                            \
        unsigned ws = w_base + (((t) & 1) * 4096 + wr * 256 + wc) * 4;                 \
        if (cb >= 16) {                                                                \
            const float* src = W + (size_t)(k0 + wr) * 1024 + cbase + wc;              \
            cp16(ws, src); cp16(ws + 16, src + 4);                                     \
            cp16(ws + 32, src + 8); cp16(ws + 48, src + 12);                           \
        } else {                                                                       \
            float* wsd = w_smb + ((t) & 1) * 4096 + wr * 256 + wc;                     \
            if (wr < cb) {                                                             \
                const float* src = W + (size_t)(k0 + wr) * 1024 + cbase + wc;          \
                for (int i = 0; i < 16; i++) wsd[i] = src[i];                          \
            } else {                                                                   \
                for (int i = 0; i < 16; i++) wsd[i] = 0.f;                             \
            }                                                                          \
        }                                                                              \
        asm volatile("cp.async.commit_group;");                                        \
    } while (0)

#define LOADA(t) do {                                                                  \
        int k0 = kbeg + (t) * 16;                                                      \
        int cb = kend - k0;                                                            \
        if (cb >= 16) {                                                                \
            a4 = *(const float4*)(A + (size_t)am * K + k0 + ak);                       \
        } else {                                                                       \
            float av[4];                                                               \
            for (int i = 0; i < 4; i++)                                                \
                av[i] = (ak + i < cb) ? A[(size_t)am * K + k0 + ak + i] : 0.f;         \
            a4 = make_float4(av[0], av[1], av[2], av[3]);                              \
        }                                                                              \
    } while (0)

#define STSA(t) do {                                                                   \
        float* as = a_smb + ((t) & 1) * 1088;                                          \
        as[(ak + 0) * 68 + am] = a4.x; as[(ak + 1) * 68 + am] = a4.y;                  \
        as[(ak + 2) * 68 + am] = a4.z; as[(ak + 3) * 68 + am] = a4.w;                  \
    } while (0)

    PREFW(0);
    LOADA(0);
    STSA(0);
    asm volatile("cp.async.wait_group 0;");
    __syncthreads();
    for (int t = 0; t < ntiles; t++) {
        if (t + 1 < ntiles) { PREFW(t + 1); LOADA(t + 1); }
        const float* as = a_smb + (t & 1) * 1088;
        const float* ws = w_smb + (t & 1) * 4096;
#pragma unroll 4
        for (int kk = 0; kk < 16; kk++) {
            float4 w = *(const float4*)(ws + kk * 256 + cq * 4);
            unsigned long long w0x = pk2(w.x, w.x), w1x = pk2(w.y, w.y);
            unsigned long long w2x = pk2(w.z, w.z), w3x = pk2(w.w, w.w);
            const ulonglong2* ap = reinterpret_cast<const ulonglong2*>(as + kk * 68 + row0);
            ulonglong2 v0 = ap[0], v1 = ap[1], v2 = ap[2], v3 = ap[3];
            fma2(acc[0],  v0.x, w0x); fma2(acc[1],  v0.y, w0x);
            fma2(acc[2],  v1.x, w0x); fma2(acc[3],  v1.y, w0x);
            fma2(acc[4],  v2.x, w0x); fma2(acc[5],  v2.y, w0x);
            fma2(acc[6],  v3.x, w0x); fma2(acc[7],  v3.y, w0x);
            fma2(acc[8],  v0.x, w1x); fma2(acc[9],  v0.y, w1x);
            fma2(acc[10], v1.x, w1x); fma2(acc[11], v1.y, w1x);
            fma2(acc[12], v2.x, w1x); fma2(acc[13], v2.y, w1x);
            fma2(acc[14], v3.x, w1x); fma2(acc[15], v3.y, w1x);
            fma2(acc[16], v0.x, w2x); fma2(acc[17], v0.y, w2x);
            fma2(acc[18], v1.x, w2x); fma2(acc[19], v1.y, w2x);
            fma2(acc[20], v2.x, w2x); fma2(acc[21], v2.y, w2x);
            fma2(acc[22], v3.x, w2x); fma2(acc[23], v3.y, w2x);
            fma2(acc[24], v0.x, w3x); fma2(acc[25], v0.y, w3x);
            fma2(acc[26], v1.x, w3x); fma2(acc[27], v1.y, w3x);
            fma2(acc[28], v2.x, w3x); fma2(acc[29], v2.y, w3x);
            fma2(acc[30], v3.x, w3x); fma2(acc[31], v3.y, w3x);
        }
        if (t + 1 < ntiles) { STSA(t + 1); asm volatile("cp.async.wait_group 0;"); }
        __syncthreads();
    }
#undef PREFW
#undef LOADA
#undef STSA
#pragma unroll
    for (int j = 0; j < 8; j++) {
        float lo[4], hi[4];
#pragma unroll
        for (int cjj = 0; cjj < 4; cjj++) {
            unsigned l, h;
            asm("mov.b64 {%0,%1}, %2;" : "=r"(l), "=r"(h) : "l"(acc[cjj * 8 + j]));
            lo[cjj] = __uint_as_float(l); hi[cjj] = __uint_as_float(h);
        }
        *(float4*)(po + (size_t)(row0 + 2 * j) * 1024 + c0) = make_float4(lo[0], lo[1], lo[2], lo[3]);
        *(float4*)(po + (size_t)(row0 + 2 * j + 1) * 1024 + c0) = make_float4(hi[0], hi[1], hi[2], hi[3]);
    }
}

// merged noise-first(K=9408, S=42 x 224) + branch(2 mats, K=588: 11x48 + 60, 16-aligned)
__global__ void __launch_bounds__(256) k_gemm_bn(const float* __restrict__ W_pe,
                                                 const float* __restrict__ W_no) {
    __shared__ __align__(16) float a_sm[2 * 1088];
    __shared__ __align__(16) float w_sm[2 * 4096];
    int z = blockIdx.z;
    if (z < 42) {
        gemm_body(g_npool, W_no, g_part + 1572864 + (size_t)z * 65536, 9408, z * 224, z * 224 + 224, a_sm, w_sm);
    } else {
        int zz = z - 42;
        int mat = zz / 12, y = zz - mat * 12;
        const float* A = mat ? g_meanO : g_meanS;
        int kbeg = y * 48;
        int kend = (y == 11) ? 588 : kbeg + 48;
        gemm_body(A, W_pe, g_part + (size_t)zz * 65536, 588, kbeg, kend, a_sm, w_sm);
    }
}
// generic: asel 3=g_feats 4=g_t
__global__ void __launch_bounds__(256) k_gemm(int asel, const float* __restrict__ W0,
                                              const float* __restrict__ W1, int use_Mt,
                                              int K, int S, int nrt) {
    __shared__ __align__(16) float a_sm[2 * 1088];
    __shared__ __align__(16) float w_sm[2 * 4096];
    int z = blockIdx.z;
    int mat = z / nrt, rt = z - mat * nrt;
    const float* A = ((asel == 3) ? g_feats : g_t) + (size_t)(rt * 64) * K;
    const float* W = use_Mt ? g_Mt : (mat ? W1 : W0);
    int kslice = K / S, kbeg = blockIdx.y * kslice;
    float* po = g_part + ((size_t)(mat * S + blockIdx.y) * nrt + rt) * 65536;
    gemm_body(A, W, po, K, kbeg, kbeg + kslice, a_sm, w_sm);
}

// ---------- merged reduce: branch LN (+pos-emb) and noise ----------
__global__ void __launch_bounds__(256) k_reduce_bn(const float* __restrict__ gg,
                                                   const float* __restrict__ bb) {
    int bx = blockIdx.x;
    if (bx < 128) {
        int z = bx >> 6, b = bx & 63;
        const float* base = g_part + (size_t)z * 12 * 65536 + (size_t)b * 1024;
        float v[4], s = 0.f, q = 0.f;
#pragma unroll
        for (int i = 0; i < 4; i++) {
            int d = threadIdx.x + i * 256;
            float mp = 0.f;
#pragma unroll
            for (int p = 0; p < 8; p++) mp += g_mpart[p * 1024 + d];
            float xv = mp * (1.0f / 256.0f);
#pragma unroll
            for (int y = 0; y < 12; y++) xv += base[(size_t)y * 65536 + d];
            v[i] = xv; s += xv; q += xv * xv;
        }
        s = blk_sum256(s); q = blk_sum256(q);
        float mean = s * (1.0f / 1024.0f);
        float inv = rsqrtf(q * (1.0f / 1024.0f) - mean * mean + 1e-5f);
#pragma unroll
        for (int i = 0; i < 4; i++) {
            int d = threadIdx.x + i * 256;
            g_feats[((size_t)b * 3 + z) * 1024 + d] = (v[i] - mean) * inv * gg[d] + bb[d];
        }
    } else {
        int i = (bx - 128) * 256 + threadIdx.x;    // 65536 noise elements
        float s = 0.f;
#pragma unroll
        for (int y = 0; y < 42; y++) s += g_part[1572864 + (size_t)y * 65536 + i];
        int b = i >> 10, d = i & 1023;
        g_feats[((size_t)b * 3 + 2) * 1024 + d] = s;
    }
}

// ---------- token LN + inline 16-way DCT partial reduce + fc/vproj dots ----------
__global__ void __launch_bounds__(256) k_ln_tokens(const float* __restrict__ gg,
                                                   const float* __restrict__ bb,
                                                   const float* __restrict__ wfc) {
    int r = blockIdx.x;
    float x[4], s = 0.f, q = 0.f;
#pragma unroll
    for (int i = 0; i < 4; i++) {
        int d = threadIdx.x + i * 256;
        float xv = 0.f;
#pragma unroll
        for (int y = 0; y < 16; y++) xv += g_part[(size_t)y * 196608 + (size_t)r * 1024 + d];
        x[i] = xv; s += xv; q += xv * xv;
    }
    s = blk_sum256(s); q = blk_sum256(q);
    float mean = s * (1.0f / 1024.0f);
    float inv = rsqrtf(q * (1.0f / 1024.0f) - mean * mean + 1e-5f);
    float dt = 0.f, dv = 0.f;
#pragma unroll
    for (int i = 0; i < 4; i++) {
        int d = threadIdx.x + i * 256;
        float tv = (x[i] - mean) * inv * gg[d] + bb[d];
        g_t[(size_t)r * 1024 + d] = tv;
        dt += x[i] * wfc[d];
        dv += tv * g_wvofc[d];
    }
    dt = blk_sum256(dt); dv = blk_sum256(dv);
    if (threadIdx.x == 0) { g_tokfc[r] = dt; g_vproj[r] = dv; }
}

// ---------- final: inline 8-way q/k partial reduce + 3x3 attention ----------
__global__ void __launch_bounds__(256) k_final(const float* __restrict__ bfc,
                                               float* __restrict__ out) {
    int b = blockIdx.x, tid = threadIdx.x;
    float a9[9];
#pragma unroll
    for (int p = 0; p < 9; p++) a9[p] = 0.f;
#pragma unroll
    for (int i = 0; i < 4; i++) {
        int d = tid + i * 256;
        float qv[3], kv[3];
#pragma unroll
        for (int n = 0; n < 3; n++) {
            size_t base = (size_t)(b * 3 + n) * 1024 + d;
            float sq = 0.f, sk = 0.f;
#pragma unroll
            for (int y = 0; y < 8; y++) {
                sq += g_part[(size_t)y * 196608 + base];
                sk += g_part[1572864 + (size_t)y * 196608 + base];
            }
            qv[n] = sq; kv[n] = sk;
        }
#pragma unroll
        for (int n = 0; n < 3; n++)
#pragma unroll
            for (int m = 0; m < 3; m++) a9[n * 3 + m] += qv[n] * kv[m];
    }
    __shared__ float red[8 * 9];
    int lane = tid & 31, w = tid >> 5;
#pragma unroll
    for (int p = 0; p < 9; p++) {
        float v = a9[p];
        for (int o = 16; o; o >>= 1) v += __shfl_xor_sync(0xffffffffu, v, o);
        if (!lane) red[w * 9 + p] = v;
    }
    __syncthreads();
    if (tid == 0) {
        float s[9];
#pragma unroll
        for (int p = 0; p < 9; p++) {
            float v = 0.f;
#pragma unroll
            for (int ww = 0; ww < 8; ww++) v += red[ww * 9 + p];
            s[p] = v;
        }
        float w0 = 0.f, w1 = 0.f, w2 = 0.f;
#pragma unroll
        for (int n = 0; n < 3; n++) {
            float a = s[n * 3] * 0.03125f, c = s[n * 3 + 1] * 0.03125f, e = s[n * 3 + 2] * 0.03125f;
            float mx = fmaxf(a, fmaxf(c, e));
            float e0 = expf(a - mx), e1 = expf(c - mx), e2 = expf(e - mx);
            float is = 1.0f / (e0 + e1 + e2);
            w0 += e0 * is; w1 += e1 * is; w2 += e2 * is;
        }
        float r = (w0 * g_vproj[b * 3] + w1 * g_vproj[b * 3 + 1] + w2 * g_vproj[b * 3 + 2]) * (1.0f / 3.0f);
        r += (g_tokfc[b * 3] + g_tokfc[b * 3 + 1] + g_tokfc[b * 3 + 2]) * (1.0f / 3.0f);
        out[b] = r + bfc[0];
    }
}

// ---------- launch ----------
extern "C" void kernel_launch(void* const* d_in, const int* in_sizes, int n_in,
                              void* d_out, int out_size) {
    (void)in_sizes; (void)n_in; (void)out_size;
    const float* x    = (const float*)d_in[0];
    const int*   sidx = (const int*)d_in[1];
    const int*   rot  = (const int*)d_in[2];
    const int*   fh   = (const int*)d_in[3];
    const int*   fw   = (const int*)d_in[4];
    const float* W_pe = (const float*)d_in[5];
    const float* pos  = (const float*)d_in[6];
    const float* ln_g = (const float*)d_in[7];
    const float* ln_b = (const float*)d_in[8];
    const float* W_no = (const float*)d_in[9];
    const float* Wq   = (const float*)d_in[10];
    const float* Wk   = (const float*)d_in[11];
    const float* Wv   = (const float*)d_in[12];
    const float* Wo   = (const float*)d_in[13];
    const float* ah_g = (const float*)d_in[14];
    const float* ah_b = (const float*)d_in[15];
    const float* W_fc = (const float*)d_in[16];
    const float* b_fc = (const float*)d_in[17];
    float* out = (float*)d_out;

    cudaFuncSetAttribute(k_planes, cudaFuncAttributeMaxDynamicSharedMemorySize, 217088);

    k_setup<<<4360, 256>>>(pos, Wo, W_fc);
    k_wvofc<<<256, 256>>>(Wv);
    k_planes<<<192, 1024, 216832>>>(x, sidx, rot, fh, fw);
    k_gemm_bn<<<dim3(4, 1, 66), 256>>>(W_pe, W_no);
    k_reduce_bn<<<384, 256>>>(ln_g, ln_b);
    k_gemm<<<dim3(4, 16, 3), 256>>>(3, W_pe, W_pe, 1, 1024, 16, 3);  // DCT
    k_ln_tokens<<<192, 256>>>(ah_g, ah_b, W_fc);
    k_gemm<<<dim3(4, 8, 6), 256>>>(4, Wq, Wk, 0, 1024, 8, 3);        // q,k
    k_final<<<64, 256>>>(b_fc, out);
}

// round 15
// speedup vs baseline: 1.1304x; 1.1304x over previous
#include <cuda_runtime.h>
#include <cuda_bf16.h>

// ---------- static device scratch ----------
__device__ float g_Mt[1024 * 1024];
__device__ float g_mpart[8 * 1024];
__device__ float g_meanS[64 * 588];
__device__ float g_meanO[64 * 588];
__device__ float g_npool[64 * 9408];
__device__ float g_part[4718592];
__device__ float g_feats[64 * 3 * 1024];
__device__ float g_t[192 * 1024];
__device__ float g_wofc[1024];
__device__ float g_wvofc[1024];
__device__ float g_vproj[192];
__device__ float g_tokfc[192];

// ---------- helpers ----------
__device__ __forceinline__ unsigned long long pk2(float lo, float hi) {
    unsigned long long r;
    asm("mov.b64 %0,{%1,%2};" : "=l"(r) : "r"(__float_as_uint(lo)), "r"(__float_as_uint(hi)));
    return r;
}
__device__ __forceinline__ void fma2(unsigned long long& acc, unsigned long long a, unsigned long long b) {
    asm("fma.rn.f32x2 %0, %1, %2, %0;" : "+l"(acc) : "l"(a), "l"(b));
}
__device__ __forceinline__ float blk_sum256(float v) {
    __shared__ float sb[8];
    int lane = threadIdx.x & 31, w = threadIdx.x >> 5;
    for (int o = 16; o; o >>= 1) v += __shfl_xor_sync(0xffffffffu, v, o);
    if (!lane) sb[w] = v;
    __syncthreads();
    float t = 0.f;
#pragma unroll
    for (int i = 0; i < 8; i++) t += sb[i];
    __syncthreads();
    return t;
}

// ---------- fused setup: DCT matrix + pos-emb partials + Wo@Wfc ----------
__global__ void __launch_bounds__(256) k_setup(const float* __restrict__ pos,
                                               const float* __restrict__ Wo,
                                               const float* __restrict__ Wfc) {
    int bx = blockIdx.x, tid = threadIdx.x;
    if (bx < 4096) {                               // DCT matrix, JAX fp32 arg rounding
        int idx = bx * 256 + tid;
        int d = idx >> 10, k = idx & 1023;
        float t1 = __fmul_rn(3.14159265358979323846f, (float)d + 0.5f);
        float t2 = __fmul_rn(t1, (float)k);
        float t3 = __fmul_rn(t2, 0.0009765625f);
        float q = rintf(t3 * 0.6366197723675814f);
        float r = __fmaf_rn(q, -1.57079637050628662109375f, t3);
        r = __fmaf_rn(q, 4.37113900018624283e-8f, r);
        int qi = ((int)q) & 3;
        float v = (qi & 1) ? sinf(r) : cosf(r);
        float c = (qi == 1 || qi == 2) ? -v : v;
        float s = (k == 0) ? 0.03125f : 0.044194173824159216f;
        g_Mt[idx] = c * s;
    } else if (bx < 4104) {                        // pos-emb partial sums (32 tokens each)
        int p = bx - 4096;
#pragma unroll
        for (int qq = 0; qq < 4; qq++) {
            int d = tid + qq * 256;
            float s = 0.f;
#pragma unroll 4
            for (int t = 0; t < 32; t++) s += pos[(p * 32 + t) * 1024 + d];
            g_mpart[p * 1024 + d] = s;
        }
    } else {                                       // wofc = Wo @ Wfc (2 warps per row)
        int bl = bx - 4104;
        int row = bl * 4 + (tid >> 6);
        int l64 = tid & 63;
        const float* wr = Wo + (size_t)row * 1024;
        float s = 0.f;
#pragma unroll 16
        for (int it = 0; it < 16; it++) s += wr[it * 64 + l64] * Wfc[it * 64 + l64];
        for (int o = 16; o; o >>= 1) s += __shfl_xor_sync(0xffffffffu, s, o);
        __shared__ float ss[8];
        if (!(tid & 31)) ss[tid >> 5] = s;
        __syncthreads();
        if (tid < 4) g_wofc[bl * 4 + tid] = ss[2 * tid] + ss[2 * tid + 1];
    }
}

// ---------- fused per-plane: float4 load to smem, pools + orig bins + shuffled bins ----------
__global__ void __launch_bounds__(1024) k_planes(const float* __restrict__ x,
                                                 const int* __restrict__ sidx,
                                                 const int* __restrict__ rot,
                                                 const int* __restrict__ fh,
                                                 const int* __restrict__ fw) {
    extern __shared__ float sm[];
    float* pl = sm;                 // 224 rows x 228 stride (16B-aligned rows)
    float* p4 = sm + 228 * 224;     // 56x56
    int bc = blockIdx.x, b = bc / 3, c = bc % 3, tid = threadIdx.x;
    const float* plane = x + (size_t)bc * 50176;

    __shared__ int sm_m[49], sm_k[49], sm_h[49], sm_w[49];
    if (tid < 49) {
        sm_m[tid] = sidx[tid];
        sm_k[tid] = rot[b * 49 + tid];
        sm_h[tid] = fh[b * 49 + tid];
        sm_w[tid] = fw[b * 49 + tid];
    }
    for (int idx4 = tid; idx4 < 12544; idx4 += 1024) {      // 224*56 float4
        int i = idx4 / 56, j4 = idx4 - i * 56;
        *(float4*)(pl + i * 228 + j4 * 4) = *(const float4*)(plane + i * 224 + j4 * 4);
    }
    __syncthreads();
    for (int cell = tid; cell < 3136; cell += 1024) {
        int i = cell / 56, j = cell - (cell / 56) * 56;
        const float* p = pl + (i * 4) * 228 + j * 4;
        float s = 0.f;
#pragma unroll
        for (int r = 0; r < 4; r++)
            s += p[r * 228] + p[r * 228 + 1] + p[r * 228 + 2] + p[r * 228 + 3];
        p4[cell] = s;
    }
    __syncthreads();
    for (int cell = tid; cell < 3136; cell += 1024) {
        int i = cell / 56, j = cell - (cell / 56) * 56;
        int i0 = i & ~1, j0 = j & ~1;
        float s8 = p4[i0 * 56 + j0] + p4[i0 * 56 + j0 + 1] +
                   p4[(i0 + 1) * 56 + j0] + p4[(i0 + 1) * 56 + j0 + 1];
        g_npool[(size_t)bc * 3136 + cell] = p4[cell] * 0.0625f - s8 * 0.015625f;
    }
    if (tid < 196) {                               // original-branch bins
        int dy = tid / 14, dx = tid - (tid / 14) * 14;
        float s = 0.f;
        for (int ii = 0; ii < 16; ii++) {
            const float* row = pl + (ii * 14 + dy) * 228;
#pragma unroll
            for (int jj = 0; jj < 16; jj++) s += row[jj * 14 + dx];
        }
        g_meanO[b * 588 + c * 196 + tid] = s * (1.0f / 256.0f);
    } else if (tid >= 256 && tid < 452) {          // shuffled-branch bins (inverse map)
        int bin = tid - 256, dy = bin / 14, dx = bin - (bin / 14) * 14;
        float s = 0.f;
        for (int ii = 0; ii < 16; ii++) {
            int y = ii * 14 + dy;
            int pr = y >> 5, r = y & 31;
#pragma unroll 4
            for (int jj = 0; jj < 16; jj++) {
                int xx = jj * 14 + dx;
                int pc = xx >> 5, cc = xx & 31;
                int n = pr * 7 + pc;
                int m = sm_m[n];
                int c1 = sm_w[n] ? 31 - cc : cc;
                int r1 = sm_h[n] ? 31 - r : r;
                int k = sm_k[n], sr, sc;
                if (k == 0)      { sr = r1;      sc = c1;      }
                else if (k == 1) { sr = c1;      sc = 31 - r1; }
                else if (k == 2) { sr = 31 - r1; sc = 31 - c1; }
                else             { sr = 31 - c1; sc = r1;      }
                s += pl[((m / 7) * 32 + sr) * 228 + (m % 7) * 32 + sc];
            }
        }
        g_meanS[b * 588 + c * 196 + bin] = s * (1.0f / 256.0f);
    }
}

// ---------- GEMM body: 64 rows x 128 cols; double-buffered smem pipeline (R10 proven) ----------
// REQUIREMENT: kbeg % 4 == 0. a_sm: 2*1088 floats, w_sm: 2*2048 floats.
__device__ __forceinline__ void gemm_body(const float* __restrict__ A, const float* __restrict__ W,
                                          float* __restrict__ po, int K, int kbeg, int kend,
                                          float* a_sm, float* w_sm) {
    int tid = threadIdx.x;
    int cpair = tid & 63;
    int c0 = blockIdx.x * 128 + cpair * 2;
    int row0 = (tid >> 6) * 16;
    int am = tid >> 2, ak = (tid & 3) * 4;
    int wr = tid >> 5, wc = (tid & 31) * 4;
    int cbase = blockIdx.x * 128;

    unsigned long long acc[16];
#pragma unroll
    for (int i = 0; i < 16; i++) acc[i] = 0ULL;

    int ntiles = (kend - kbeg + 15) >> 4;
    float4 a4, w4A, w4B;

#define LOADT(t) do {                                                                  \
        int k0 = kbeg + (t) * 16;                                                      \
        int cb = kend - k0;                                                            \
        if (cb >= 16) {                                                                \
            a4  = *(const float4*)(A + (size_t)am * K + k0 + ak);                      \
            w4A = *(const float4*)(W + (size_t)(k0 + wr) * 1024 + cbase + wc);         \
            w4B = *(const float4*)(W + (size_t)(k0 + wr + 8) * 1024 + cbase + wc);     \
        } else {                                                                       \
            float av[4], wa[4], wb[4];                                                 \
            for (int i = 0; i < 4; i++) {                                              \
                av[i] = (ak + i < cb) ? A[(size_t)am * K + k0 + ak + i] : 0.f;         \
                wa[i] = (wr < cb) ? W[(size_t)(k0 + wr) * 1024 + cbase + wc + i] : 0.f;\
                wb[i] = (wr + 8 < cb) ? W[(size_t)(k0 + wr + 8) * 1024 + cbase + wc + i] : 0.f; \
            }                                                                          \
            a4 = make_float4(av[0], av[1], av[2], av[3]);                              \
            w4A = make_float4(wa[0], wa[1], wa[2], wa[3]);                             \
            w4B = make_float4(wb[0], wb[1], wb[2], wb[3]);                             \
        }                                                                              \
    } while (0)

#define STORET(bsel) do {                                                              \
        float* as = a_sm + (bsel) * 1088;                                              \
        float* ws = w_sm + (bsel) * 2048;                                              \
        as[(ak + 0) * 68 + am] = a4.x; as[(ak + 1) * 68 + am] = a4.y;                  \
        as[(ak + 2) * 68 + am] = a4.z; as[(ak + 3) * 68 + am] = a4.w;                  \
        *(float4*)(ws + wr * 128 + wc) = w4A;                                          \
        *(float4*)(ws + (wr + 8) * 128 + wc) = w4B;                                    \
    } while (0)

    LOADT(0);
    STORET(0);
    __syncthreads();
    for (int t = 0; t < ntiles; t++) {
        if (t + 1 < ntiles) LOADT(t + 1);
        const float* as = a_sm + (t & 1) * 1088;
        const float* ws = w_sm + (t & 1) * 2048;
#pragma unroll 4
        for (int kk = 0; kk < 16; kk++) {
            float2 w = ((const float2*)(ws + kk * 128))[cpair];
            unsigned long long w0x = pk2(w.x, w.x), w1x = pk2(w.y, w.y);
            const ulonglong2* ap = reinterpret_cast<const ulonglong2*>(as + kk * 68 + row0);
            ulonglong2 v0 = ap[0], v1 = ap[1], v2 = ap[2], v3 = ap[3];
            fma2(acc[0], v0.x, w0x); fma2(acc[1], v0.y, w0x);
            fma2(acc[2], v1.x, w0x); fma2(acc[3], v1.y, w0x);
            fma2(acc[4], v2.x, w0x); fma2(acc[5], v2.y, w0x);
            fma2(acc[6], v3.x, w0x); fma2(acc[7], v3.y, w0x);
            fma2(acc[8],  v0.x, w1x); fma2(acc[9],  v0.y, w1x);
            fma2(acc[10], v1.x, w1x); fma2(acc[11], v1.y, w1x);
            fma2(acc[12], v2.x, w1x); fma2(acc[13], v2.y, w1x);
            fma2(acc[14], v3.x, w1x); fma2(acc[15], v3.y, w1x);
        }
        if (t + 1 < ntiles) STORET((t + 1) & 1);
        __syncthreads();
    }
#undef LOADT
#undef STORET
#pragma unroll
    for (int j = 0; j < 8; j++) {
        unsigned l0, h0, l1, h1;
        asm("mov.b64 {%0,%1}, %2;" : "=r"(l0), "=r"(h0) : "l"(acc[j]));
        asm("mov.b64 {%0,%1}, %2;" : "=r"(l1), "=r"(h1) : "l"(acc[8 + j]));
        float2 r0 = make_float2(__uint_as_float(l0), __uint_as_float(l1));
        float2 r1 = make_float2(__uint_as_float(h0), __uint_as_float(h1));
        *(float2*)(po + (size_t)(row0 + 2 * j) * 1024 + c0) = r0;
        *(float2*)(po + (size_t)(row0 + 2 * j + 1) * 1024 + c0) = r1;
    }
}

// merged noise-first(K=9408, S=42 x 224) + branch(2 mats, K=588: 11x48 + 60, 16-aligned)
__global__ void __launch_bounds__(256) k_gemm_bn(const float* __restrict__ W_pe,
                                                 const float* __restrict__ W_no) {
    __shared__ __align__(16) float a_sm[2 * 1088];
    __shared__ __align__(16) float w_sm[2 * 2048];
    int z = blockIdx.z;
    if (z < 42) {
        gemm_body(g_npool, W_no, g_part + 1572864 + (size_t)z * 65536, 9408, z * 224, z * 224 + 224, a_sm, w_sm);
    } else {
        int zz = z - 42;
        int mat = zz / 12, y = zz - mat * 12;
        const float* A = mat ? g_meanO : g_meanS;
        int kbeg = y * 48;
        int kend = (y == 11) ? 588 : kbeg + 48;
        gemm_body(A, W_pe, g_part + (size_t)zz * 65536, 588, kbeg, kend, a_sm, w_sm);
    }
}
// generic: asel 3=g_feats 4=g_t
__global__ void __launch_bounds__(256) k_gemm(int asel, const float* __restrict__ W0,
                                              const float* __restrict__ W1, int use_Mt,
                                              int K, int S, int nrt) {
    __shared__ __align__(16) float a_sm[2 * 1088];
    __shared__ __align__(16) float w_sm[2 * 2048];
    int z = blockIdx.z;
    int mat = z / nrt, rt = z - mat * nrt;
    const float* A = ((asel == 3) ? g_feats : g_t) + (size_t)(rt * 64) * K;
    const float* W = use_Mt ? g_Mt : (mat ? W1 : W0);
    int kslice = K / S, kbeg = blockIdx.y * kslice;
    float* po = g_part + ((size_t)(mat * S + blockIdx.y) * nrt + rt) * 65536;
    gemm_body(A, W, po, K, kbeg, kbeg + kslice, a_sm, w_sm);
}

// ---------- merged reduce: branch LN (+pos-emb), noise, and Wv@(Wo@Wfc) ----------
__global__ void __launch_bounds__(256) k_reduce_bn(const float* __restrict__ gg,
                                                   const float* __restrict__ bb,
                                                   const float* __restrict__ Wv) {
    int bx = blockIdx.x;
    if (bx < 128) {
        int z = bx >> 6, b = bx & 63;
        const float* base = g_part + (size_t)z * 12 * 65536 + (size_t)b * 1024;
        float v[4], s = 0.f, q = 0.f;
#pragma unroll
        for (int i = 0; i < 4; i++) {
            int d = threadIdx.x + i * 256;
            float mp = 0.f;
#pragma unroll
            for (int p = 0; p < 8; p++) mp += g_mpart[p * 1024 + d];
            float xv = mp * (1.0f / 256.0f);
#pragma unroll
            for (int y = 0; y < 12; y++) xv += base[(size_t)y * 65536 + d];
            v[i] = xv; s += xv; q += xv * xv;
        }
        s = blk_sum256(s); q = blk_sum256(q);
        float mean = s * (1.0f / 1024.0f);
        float inv = rsqrtf(q * (1.0f / 1024.0f) - mean * mean + 1e-5f);
#pragma unroll
        for (int i = 0; i < 4; i++) {
            int d = threadIdx.x + i * 256;
            g_feats[((size_t)b * 3 + z) * 1024 + d] = (v[i] - mean) * inv * gg[d] + bb[d];
        }
    } else if (bx < 384) {
        int i = (bx - 128) * 256 + threadIdx.x;    // 65536 noise elements
        float s = 0.f;
#pragma unroll
        for (int y = 0; y < 42; y++) s += g_part[1572864 + (size_t)y * 65536 + i];
        int b = i >> 10, d = i & 1023;
        g_feats[((size_t)b * 3 + 2) * 1024 + d] = s;
    } else {                                       // wvofc = Wv @ wofc (2 warps per row)
        int bl = bx - 384;
        int row = bl * 4 + (threadIdx.x >> 6), l64 = threadIdx.x & 63;
        const float* wr = Wv + (size_t)row * 1024;
        float s = 0.f;
#pragma unroll 16
        for (int it = 0; it < 16; it++) s += wr[it * 64 + l64] * g_wofc[it * 64 + l64];
        for (int o = 16; o; o >>= 1) s += __shfl_xor_sync(0xffffffffu, s, o);
        __shared__ float ss[8];
        if (!(threadIdx.x & 31)) ss[threadIdx.x >> 5] = s;
        __syncthreads();
        if (threadIdx.x < 4) g_wvofc[bl * 4 + threadIdx.x] = ss[2 * threadIdx.x] + ss[2 * threadIdx.x + 1];
    }
}

// ---------- token LN + inline 16-way DCT partial reduce + fc/vproj dots ----------
__global__ void __launch_bounds__(256) k_ln_tokens(const float* __restrict__ gg,
                                                   const float* __restrict__ bb,
                                                   const float* __restrict__ wfc) {
    int r = blockIdx.x;
    float x[4], s = 0.f, q = 0.f;
#pragma unroll
    for (int i = 0; i < 4; i++) {
        int d = threadIdx.x + i * 256;
        float xv = 0.f;
#pragma unroll
        for (int y = 0; y < 16; y++) xv += g_part[(size_t)y * 196608 + (size_t)r * 1024 + d];
        x[i] = xv; s += xv; q += xv * xv;
    }
    s = blk_sum256(s); q = blk_sum256(q);
    float mean = s * (1.0f / 1024.0f);
    float inv = rsqrtf(q * (1.0f / 1024.0f) - mean * mean + 1e-5f);
    float dt = 0.f, dv = 0.f;
#pragma unroll
    for (int i = 0; i < 4; i++) {
        int d = threadIdx.x + i * 256;
        float tv = (x[i] - mean) * inv * gg[d] + bb[d];
        g_t[(size_t)r * 1024 + d] = tv;
        dt += x[i] * wfc[d];
        dv += tv * g_wvofc[d];
    }
    dt = blk_sum256(dt); dv = blk_sum256(dv);
    if (threadIdx.x == 0) { g_tokfc[r] = dt; g_vproj[r] = dv; }
}

// ---------- final: 1024-thread inline 8-way q/k partial reduce + 3x3 attention ----------
__global__ void __launch_bounds__(1024) k_final(const float* __restrict__ bfc,
                                                float* __restrict__ out) {
    int b = blockIdx.x, tid = threadIdx.x;     // tid == d
    float qv[3], kv[3];
#pragma unroll
    for (int n = 0; n < 3; n++) {
        size_t base = (size_t)(b * 3 + n) * 1024 + tid;
        float sq = 0.f, sk = 0.f;
#pragma unroll
        for (int y = 0; y < 8; y++) {
            sq += g_part[(size_t)y * 196608 + base];
            sk += g_part[1572864 + (size_t)y * 196608 + base];
        }
        qv[n] = sq; kv[n] = sk;
    }
    float a9[9];
#pragma unroll
    for (int n = 0; n < 3; n++)
#pragma unroll
        for (int m = 0; m < 3; m++) a9[n * 3 + m] = qv[n] * kv[m];
    __shared__ float red[32 * 9];
    int lane = tid & 31, w = tid >> 5;
#pragma unroll
    for (int p = 0; p < 9; p++) {
        float v = a9[p];
        for (int o = 16; o; o >>= 1) v += __shfl_xor_sync(0xffffffffu, v, o);
        if (!lane) red[w * 9 + p] = v;
    }
    __syncthreads();
    if (tid == 0) {
        float s[9];
#pragma unroll
        for (int p = 0; p < 9; p++) {
            float v = 0.f;
#pragma unroll
            for (int ww = 0; ww < 32; ww++) v += red[ww * 9 + p];
            s[p] = v;
        }
        float w0 = 0.f, w1 = 0.f, w2 = 0.f;
#pragma unroll
        for (int n = 0; n < 3; n++) {
            float a = s[n * 3] * 0.03125f, c = s[n * 3 + 1] * 0.03125f, e = s[n * 3 + 2] * 0.03125f;
            float mx = fmaxf(a, fmaxf(c, e));
            float e0 = expf(a - mx), e1 = expf(c - mx), e2 = expf(e - mx);
            float is = 1.0f / (e0 + e1 + e2);
            w0 += e0 * is; w1 += e1 * is; w2 += e2 * is;
        }
        float r = (w0 * g_vproj[b * 3] + w1 * g_vproj[b * 3 + 1] + w2 * g_vproj[b * 3 + 2]) * (1.0f / 3.0f);
        r += (g_tokfc[b * 3] + g_tokfc[b * 3 + 1] + g_tokfc[b * 3 + 2]) * (1.0f / 3.0f);
        out[b] = r + bfc[0];
    }
}

// ---------- launch ----------
extern "C" void kernel_launch(void* const* d_in, const int* in_sizes, int n_in,
                              void* d_out, int out_size) {
    (void)in_sizes; (void)n_in; (void)out_size;
    const float* x    = (const float*)d_in[0];
    const int*   sidx = (const int*)d_in[1];
    const int*   rot  = (const int*)d_in[2];
    const int*   fh   = (const int*)d_in[3];
    const int*   fw   = (const int*)d_in[4];
    const float* W_pe = (const float*)d_in[5];
    const float* pos  = (const float*)d_in[6];
    const float* ln_g = (const float*)d_in[7];
    const float* ln_b = (const float*)d_in[8];
    const float* W_no = (const float*)d_in[9];
    const float* Wq   = (const float*)d_in[10];
    const float* Wk   = (const float*)d_in[11];
    const float* Wv   = (const float*)d_in[12];
    const float* Wo   = (const float*)d_in[13];
    const float* ah_g = (const float*)d_in[14];
    const float* ah_b = (const float*)d_in[15];
    const float* W_fc = (const float*)d_in[16];
    const float* b_fc = (const float*)d_in[17];
    float* out = (float*)d_out;

    cudaFuncSetAttribute(k_planes, cudaFuncAttributeMaxDynamicSharedMemorySize, 217088);

    k_setup<<<4360, 256>>>(pos, Wo, W_fc);
    k_planes<<<192, 1024, 216832>>>(x, sidx, rot, fh, fw);
    k_gemm_bn<<<dim3(8, 1, 66), 256>>>(W_pe, W_no);
    k_reduce_bn<<<640, 256>>>(ln_g, ln_b, Wv);
    k_gemm<<<dim3(8, 16, 3), 256>>>(3, W_pe, W_pe, 1, 1024, 16, 3);  // DCT
    k_ln_tokens<<<192, 256>>>(ah_g, ah_b, W_fc);
    k_gemm<<<dim3(8, 8, 6), 256>>>(4, Wq, Wk, 0, 1024, 8, 3);        // q,k
    k_final<<<64, 1024>>>(b_fc, out);
}

// round 16
// speedup vs baseline: 1.2073x; 1.0680x over previous
#include <cuda_runtime.h>
#include <cuda_bf16.h>

// ---------- static device scratch ----------
__device__ float g_Mt[1024 * 1024];
__device__ float g_mpart[8 * 1024];
__device__ float g_meanS[64 * 588];
__device__ float g_meanO[64 * 588];
__device__ float g_npool[64 * 9408];
__device__ float g_part[4718592];
__device__ float g_feats[64 * 3 * 1024];
__device__ float g_t[192 * 1024];
__device__ float g_wofc[1024];
__device__ float g_wvofc[1024];
__device__ float g_vproj[192];
__device__ float g_tokfc[192];

// ---------- helpers ----------
__device__ __forceinline__ unsigned long long pk2(float lo, float hi) {
    unsigned long long r;
    asm("mov.b64 %0,{%1,%2};" : "=l"(r) : "r"(__float_as_uint(lo)), "r"(__float_as_uint(hi)));
    return r;
}
__device__ __forceinline__ void fma2(unsigned long long& acc, unsigned long long a, unsigned long long b) {
    asm("fma.rn.f32x2 %0, %1, %2, %0;" : "+l"(acc) : "l"(a), "l"(b));
}
__device__ __forceinline__ float blk_sum256(float v) {
    __shared__ float sb[8];
    int lane = threadIdx.x & 31, w = threadIdx.x >> 5;
    for (int o = 16; o; o >>= 1) v += __shfl_xor_sync(0xffffffffu, v, o);
    if (!lane) sb[w] = v;
    __syncthreads();
    float t = 0.f;
#pragma unroll
    for (int i = 0; i < 8; i++) t += sb[i];
    __syncthreads();
    return t;
}

// ---------- fused setup: DCT matrix + pos-emb partials + Wo@Wfc ----------
__global__ void __launch_bounds__(256) k_setup(const float* __restrict__ pos,
                                               const float* __restrict__ Wo,
                                               const float* __restrict__ Wfc) {
    int bx = blockIdx.x, tid = threadIdx.x;
    if (bx < 4096) {                               // DCT matrix, JAX fp32 arg rounding
        int idx = bx * 256 + tid;
        int d = idx >> 10, k = idx & 1023;
        float t1 = __fmul_rn(3.14159265358979323846f, (float)d + 0.5f);
        float t2 = __fmul_rn(t1, (float)k);
        float t3 = __fmul_rn(t2, 0.0009765625f);
        float q = rintf(t3 * 0.6366197723675814f);
        float r = __fmaf_rn(q, -1.57079637050628662109375f, t3);
        r = __fmaf_rn(q, 4.37113900018624283e-8f, r);
        int qi = ((int)q) & 3;
        float v = (qi & 1) ? sinf(r) : cosf(r);
        float c = (qi == 1 || qi == 2) ? -v : v;
        float s = (k == 0) ? 0.03125f : 0.044194173824159216f;
        g_Mt[idx] = c * s;
    } else if (bx < 4104) {                        // pos-emb partial sums (32 tokens each)
        int p = bx - 4096;
#pragma unroll
        for (int qq = 0; qq < 4; qq++) {
            int d = tid + qq * 256;
            float s = 0.f;
#pragma unroll 4
            for (int t = 0; t < 32; t++) s += pos[(p * 32 + t) * 1024 + d];
            g_mpart[p * 1024 + d] = s;
        }
    } else {                                       // wofc = Wo @ Wfc (2 warps per row)
        int bl = bx - 4104;
        int row = bl * 4 + (tid >> 6);
        int l64 = tid & 63;
        const float* wr = Wo + (size_t)row * 1024;
        float s = 0.f;
#pragma unroll 16
        for (int it = 0; it < 16; it++) s += wr[it * 64 + l64] * Wfc[it * 64 + l64];
        for (int o = 16; o; o >>= 1) s += __shfl_xor_sync(0xffffffffu, s, o);
        __shared__ float ss[8];
        if (!(tid & 31)) ss[tid >> 5] = s;
        __syncthreads();
        if (tid < 4) g_wofc[bl * 4 + tid] = ss[2 * tid] + ss[2 * tid + 1];
    }
}

// ---------- fused per-plane: float4 load to smem, pools + orig bins + shuffled bins ----------
__global__ void __launch_bounds__(1024) k_planes(const float* __restrict__ x,
                                                 const int* __restrict__ sidx,
                                                 const int* __restrict__ rot,
                                                 const int* __restrict__ fh,
                                                 const int* __restrict__ fw) {
    extern __shared__ float sm[];
    float* pl = sm;                 // 224 rows x 228 stride (16B-aligned rows)
    float* p4 = sm + 228 * 224;     // 56x56
    int bc = blockIdx.x, b = bc / 3, c = bc % 3, tid = threadIdx.x;
    const float* plane = x + (size_t)bc * 50176;

    __shared__ int sm_m[49], sm_k[49], sm_h[49], sm_w[49];
    if (tid < 49) {
        sm_m[tid] = sidx[tid];
        sm_k[tid] = rot[b * 49 + tid];
        sm_h[tid] = fh[b * 49 + tid];
        sm_w[tid] = fw[b * 49 + tid];
    }
    for (int idx4 = tid; idx4 < 12544; idx4 += 1024) {      // 224*56 float4
        int i = idx4 / 56, j4 = idx4 - i * 56;
        *(float4*)(pl + i * 228 + j4 * 4) = *(const float4*)(plane + i * 224 + j4 * 4);
    }
    __syncthreads();
    for (int cell = tid; cell < 3136; cell += 1024) {
        int i = cell / 56, j = cell - (cell / 56) * 56;
        const float* p = pl + (i * 4) * 228 + j * 4;
        float s = 0.f;
#pragma unroll
        for (int r = 0; r < 4; r++)
            s += p[r * 228] + p[r * 228 + 1] + p[r * 228 + 2] + p[r * 228 + 3];
        p4[cell] = s;
    }
    __syncthreads();
    for (int cell = tid; cell < 3136; cell += 1024) {
        int i = cell / 56, j = cell - (cell / 56) * 56;
        int i0 = i & ~1, j0 = j & ~1;
        float s8 = p4[i0 * 56 + j0] + p4[i0 * 56 + j0 + 1] +
                   p4[(i0 + 1) * 56 + j0] + p4[(i0 + 1) * 56 + j0 + 1];
        g_npool[(size_t)bc * 3136 + cell] = p4[cell] * 0.0625f - s8 * 0.015625f;
    }
    if (tid < 196) {                               // original-branch bins
        int dy = tid / 14, dx = tid - (tid / 14) * 14;
        float s = 0.f;
        for (int ii = 0; ii < 16; ii++) {
            const float* row = pl + (ii * 14 + dy) * 228;
#pragma unroll
            for (int jj = 0; jj < 16; jj++) s += row[jj * 14 + dx];
        }
        g_meanO[b * 588 + c * 196 + tid] = s * (1.0f / 256.0f);
    } else if (tid >= 256 && tid < 452) {          // shuffled-branch bins (inverse map)
        int bin = tid - 256, dy = bin / 14, dx = bin - (bin / 14) * 14;
        float s = 0.f;
        for (int ii = 0; ii < 16; ii++) {
            int y = ii * 14 + dy;
            int pr = y >> 5, r = y & 31;
#pragma unroll 4
            for (int jj = 0; jj < 16; jj++) {
                int xx = jj * 14 + dx;
                int pc = xx >> 5, cc = xx & 31;
                int n = pr * 7 + pc;
                int m = sm_m[n];
                int c1 = sm_w[n] ? 31 - cc : cc;
                int r1 = sm_h[n] ? 31 - r : r;
                int k = sm_k[n], sr, sc;
                if (k == 0)      { sr = r1;      sc = c1;      }
                else if (k == 1) { sr = c1;      sc = 31 - r1; }
                else if (k == 2) { sr = 31 - r1; sc = 31 - c1; }
                else             { sr = 31 - c1; sc = r1;      }
                s += pl[((m / 7) * 32 + sr) * 228 + (m % 7) * 32 + sc];
            }
        }
        g_meanS[b * 588 + c * 196 + bin] = s * (1.0f / 256.0f);
    }
}

// ---------- GEMM body: 64 rows x 128 cols; double-buffered smem pipeline ----------
// REQUIREMENT: kbeg % 4 == 0. a_sm: 2*1088 floats, w_sm: 2*2048 floats.
__device__ __forceinline__ void gemm_body(const float* __restrict__ A, const float* __restrict__ W,
                                          float* __restrict__ po, int K, int kbeg, int kend,
                                          float* a_sm, float* w_sm) {
    int tid = threadIdx.x;
    int cpair = tid & 63;
    int c0 = blockIdx.x * 128 + cpair * 2;
    int row0 = (tid >> 6) * 16;
    int am = tid >> 2, ak = (tid & 3) * 4;
    int wr = tid >> 5, wc = (tid & 31) * 4;
    int cbase = blockIdx.x * 128;

    unsigned long long acc[16];
#pragma unroll
    for (int i = 0; i < 16; i++) acc[i] = 0ULL;

    int ntiles = (kend - kbeg + 15) >> 4;
    float4 a4, w4A, w4B;

#define LOADT(t) do {                                                                  \
        int k0 = kbeg + (t) * 16;                                                      \
        int cb = kend - k0;                                                            \
        if (cb >= 16) {                                                                \
            a4  = *(const float4*)(A + (size_t)am * K + k0 + ak);                      \
            w4A = *(const float4*)(W + (size_t)(k0 + wr) * 1024 + cbase + wc);         \
            w4B = *(const float4*)(W + (size_t)(k0 + wr + 8) * 1024 + cbase + wc);     \
        } else {                                                                       \
            float av[4], wa[4], wb[4];                                                 \
            for (int i = 0; i < 4; i++) {                                              \
                av[i] = (ak + i < cb) ? A[(size_t)am * K + k0 + ak + i] : 0.f;         \
                wa[i] = (wr < cb) ? W[(size_t)(k0 + wr) * 1024 + cbase + wc + i] : 0.f;\
                wb[i] = (wr + 8 < cb) ? W[(size_t)(k0 + wr + 8) * 1024 + cbase + wc + i] : 0.f; \
            }                                                                          \
            a4 = make_float4(av[0], av[1], av[2], av[3]);                              \
            w4A = make_float4(wa[0], wa[1], wa[2], wa[3]);                             \
            w4B = make_float4(wb[0], wb[1], wb[2], wb[3]);                             \
        }                                                                              \
    } while (0)

#define STORET(bsel) do {                                                              \
        float* as = a_sm + (bsel) * 1088;                                              \
        float* ws = w_sm + (bsel) * 2048;                                              \
        as[(ak + 0) * 68 + am] = a4.x; as[(ak + 1) * 68 + am] = a4.y;                  \
        as[(ak + 2) * 68 + am] = a4.z; as[(ak + 3) * 68 + am] = a4.w;                  \
        *(float4*)(ws + wr * 128 + wc) = w4A;                                          \
        *(float4*)(ws + (wr + 8) * 128 + wc) = w4B;                                    \
    } while (0)

    LOADT(0);
    STORET(0);
    __syncthreads();
    for (int t = 0; t < ntiles; t++) {
        if (t + 1 < ntiles) LOADT(t + 1);
        const float* as = a_sm + (t & 1) * 1088;
        const float* ws = w_sm + (t & 1) * 2048;
#pragma unroll 4
        for (int kk = 0; kk < 16; kk++) {
            float2 w = ((const float2*)(ws + kk * 128))[cpair];
            unsigned long long w0x = pk2(w.x, w.x), w1x = pk2(w.y, w.y);
            const ulonglong2* ap = reinterpret_cast<const ulonglong2*>(as + kk * 68 + row0);
            ulonglong2 v0 = ap[0], v1 = ap[1], v2 = ap[2], v3 = ap[3];
            fma2(acc[0], v0.x, w0x); fma2(acc[1], v0.y, w0x);
            fma2(acc[2], v1.x, w0x); fma2(acc[3], v1.y, w0x);
            fma2(acc[4], v2.x, w0x); fma2(acc[5], v2.y, w0x);
            fma2(acc[6], v3.x, w0x); fma2(acc[7], v3.y, w0x);
            fma2(acc[8],  v0.x, w1x); fma2(acc[9],  v0.y, w1x);
            fma2(acc[10], v1.x, w1x); fma2(acc[11], v1.y, w1x);
            fma2(acc[12], v2.x, w1x); fma2(acc[13], v2.y, w1x);
            fma2(acc[14], v3.x, w1x); fma2(acc[15], v3.y, w1x);
        }
        if (t + 1 < ntiles) STORET((t + 1) & 1);
        __syncthreads();
    }
#undef LOADT
#undef STORET
#pragma unroll
    for (int j = 0; j < 8; j++) {
        unsigned l0, h0, l1, h1;
        asm("mov.b64 {%0,%1}, %2;" : "=r"(l0), "=r"(h0) : "l"(acc[j]));
        asm("mov.b64 {%0,%1}, %2;" : "=r"(l1), "=r"(h1) : "l"(acc[8 + j]));
        float2 r0 = make_float2(__uint_as_float(l0), __uint_as_float(l1));
        float2 r1 = make_float2(__uint_as_float(h0), __uint_as_float(h1));
        *(float2*)(po + (size_t)(row0 + 2 * j) * 1024 + c0) = r0;
        *(float2*)(po + (size_t)(row0 + 2 * j + 1) * 1024 + c0) = r1;
    }
}

// merged noise-first(K=9408, S=42 x 224) + branch(2 mats, K=588: 11x48 + 60, 16-aligned)
__global__ void __launch_bounds__(256) k_gemm_bn(const float* __restrict__ W_pe,
                                                 const float* __restrict__ W_no) {
    __shared__ __align__(16) float a_sm[2 * 1088];
    __shared__ __align__(16) float w_sm[2 * 2048];
    int z = blockIdx.z;
    if (z < 42) {
        gemm_body(g_npool, W_no, g_part + 1572864 + (size_t)z * 65536, 9408, z * 224, z * 224 + 224, a_sm, w_sm);
    } else {
        int zz = z - 42;
        int mat = zz / 12, y = zz - mat * 12;
        const float* A = mat ? g_meanO : g_meanS;
        int kbeg = y * 48;
        int kend = (y == 11) ? 588 : kbeg + 48;
        gemm_body(A, W_pe, g_part + (size_t)zz * 65536, 588, kbeg, kend, a_sm, w_sm);
    }
}
// generic: asel 3=g_feats 4=g_t
__global__ void __launch_bounds__(256) k_gemm(int asel, const float* __restrict__ W0,
                                              const float* __restrict__ W1, int use_Mt,
                                              int K, int S, int nrt) {
    __shared__ __align__(16) float a_sm[2 * 1088];
    __shared__ __align__(16) float w_sm[2 * 2048];
    int z = blockIdx.z;
    int mat = z / nrt, rt = z - mat * nrt;
    const float* A = ((asel == 3) ? g_feats : g_t) + (size_t)(rt * 64) * K;
    const float* W = use_Mt ? g_Mt : (mat ? W1 : W0);
    int kslice = K / S, kbeg = blockIdx.y * kslice;
    float* po = g_part + ((size_t)(mat * S + blockIdx.y) * nrt + rt) * 65536;
    gemm_body(A, W, po, K, kbeg, kbeg + kslice, a_sm, w_sm);
}

// ---------- merged reduce: branch LN (+pos-emb), noise, and Wv@(Wo@Wfc) ----------
__global__ void __launch_bounds__(256) k_reduce_bn(const float* __restrict__ gg,
                                                   const float* __restrict__ bb,
                                                   const float* __restrict__ Wv) {
    int bx = blockIdx.x;
    if (bx < 128) {
        int z = bx >> 6, b = bx & 63;
        const float* base = g_part + (size_t)z * 12 * 65536 + (size_t)b * 1024;
        float v[4], s = 0.f, q = 0.f;
#pragma unroll
        for (int i = 0; i < 4; i++) {
            int d = threadIdx.x + i * 256;
            float mp = 0.f;
#pragma unroll
            for (int p = 0; p < 8; p++) mp += g_mpart[p * 1024 + d];
            float xv = mp * (1.0f / 256.0f);
#pragma unroll
            for (int y = 0; y < 12; y++) xv += base[(size_t)y * 65536 + d];
            v[i] = xv; s += xv; q += xv * xv;
        }
        s = blk_sum256(s); q = blk_sum256(q);
        float mean = s * (1.0f / 1024.0f);
        float inv = rsqrtf(q * (1.0f / 1024.0f) - mean * mean + 1e-5f);
#pragma unroll
        for (int i = 0; i < 4; i++) {
            int d = threadIdx.x + i * 256;
            g_feats[((size_t)b * 3 + z) * 1024 + d] = (v[i] - mean) * inv * gg[d] + bb[d];
        }
    } else if (bx < 384) {
        int i = (bx - 128) * 256 + threadIdx.x;    // 65536 noise elements
        float s = 0.f;
#pragma unroll
        for (int y = 0; y < 42; y++) s += g_part[1572864 + (size_t)y * 65536 + i];
        int b = i >> 10, d = i & 1023;
        g_feats[((size_t)b * 3 + 2) * 1024 + d] = s;
    } else {                                       // wvofc = Wv @ wofc (2 warps per row)
        int bl = bx - 384;
        int row = bl * 4 + (threadIdx.x >> 6), l64 = threadIdx.x & 63;
        const float* wr = Wv + (size_t)row * 1024;
        float s = 0.f;
#pragma unroll 16
        for (int it = 0; it < 16; it++) s += wr[it * 64 + l64] * g_wofc[it * 64 + l64];
        for (int o = 16; o; o >>= 1) s += __shfl_xor_sync(0xffffffffu, s, o);
        __shared__ float ss[8];
        if (!(threadIdx.x & 31)) ss[threadIdx.x >> 5] = s;
        __syncthreads();
        if (threadIdx.x < 4) g_wvofc[bl * 4 + threadIdx.x] = ss[2 * threadIdx.x] + ss[2 * threadIdx.x + 1];
    }
}

// ---------- token LN + inline 8-way DCT partial reduce + fc/vproj dots ----------
__global__ void __launch_bounds__(256) k_ln_tokens(const float* __restrict__ gg,
                                                   const float* __restrict__ bb,
                                                   const float* __restrict__ wfc) {
    int r = blockIdx.x;
    float x[4], s = 0.f, q = 0.f;
#pragma unroll
    for (int i = 0; i < 4; i++) {
        int d = threadIdx.x + i * 256;
        float xv = 0.f;
#pragma unroll
        for (int y = 0; y < 8; y++) xv += g_part[(size_t)y * 196608 + (size_t)r * 1024 + d];
        x[i] = xv; s += xv; q += xv * xv;
    }
    s = blk_sum256(s); q = blk_sum256(q);
    float mean = s * (1.0f / 1024.0f);
    float inv = rsqrtf(q * (1.0f / 1024.0f) - mean * mean + 1e-5f);
    float dt = 0.f, dv = 0.f;
#pragma unroll
    for (int i = 0; i < 4; i++) {
        int d = threadIdx.x + i * 256;
        float tv = (x[i] - mean) * inv * gg[d] + bb[d];
        g_t[(size_t)r * 1024 + d] = tv;
        dt += x[i] * wfc[d];
        dv += tv * g_wvofc[d];
    }
    dt = blk_sum256(dt); dv = blk_sum256(dv);
    if (threadIdx.x == 0) { g_tokfc[r] = dt; g_vproj[r] = dv; }
}

// ---------- final: 1024-thread inline 8-way q/k partial reduce + 3x3 attention ----------
__global__ void __launch_bounds__(1024) k_final(const float* __restrict__ bfc,
                                                float* __restrict__ out) {
    int b = blockIdx.x, tid = threadIdx.x;     // tid == d
    float qv[3], kv[3];
#pragma unroll
    for (int n = 0; n < 3; n++) {
        size_t base = (size_t)(b * 3 + n) * 1024 + tid;
        float sq = 0.f, sk = 0.f;
#pragma unroll
        for (int y = 0; y < 8; y++) {
            sq += g_part[(size_t)y * 196608 + base];
            sk += g_part[1572864 + (size_t)y * 196608 + base];
        }
        qv[n] = sq; kv[n] = sk;
    }
    float a9[9];
#pragma unroll
    for (int n = 0; n < 3; n++)
#pragma unroll
        for (int m = 0; m < 3; m++) a9[n * 3 + m] = qv[n] * kv[m];
    __shared__ float red[32 * 9];
    int lane = tid & 31, w = tid >> 5;
#pragma unroll
    for (int p = 0; p < 9; p++) {
        float v = a9[p];
        for (int o = 16; o; o >>= 1) v += __shfl_xor_sync(0xffffffffu, v, o);
        if (!lane) red[w * 9 + p] = v;
    }
    __syncthreads();
    if (tid == 0) {
        float s[9];
#pragma unroll
        for (int p = 0; p < 9; p++) {
            float v = 0.f;
#pragma unroll
            for (int ww = 0; ww < 32; ww++) v += red[ww * 9 + p];
            s[p] = v;
        }
        float w0 = 0.f, w1 = 0.f, w2 = 0.f;
#pragma unroll
        for (int n = 0; n < 3; n++) {
            float a = s[n * 3] * 0.03125f, c = s[n * 3 + 1] * 0.03125f, e = s[n * 3 + 2] * 0.03125f;
            float mx = fmaxf(a, fmaxf(c, e));
            float e0 = expf(a - mx), e1 = expf(c - mx), e2 = expf(e - mx);
            float is = 1.0f / (e0 + e1 + e2);
            w0 += e0 * is; w1 += e1 * is; w2 += e2 * is;
        }
        float r = (w0 * g_vproj[b * 3] + w1 * g_vproj[b * 3 + 1] + w2 * g_vproj[b * 3 + 2]) * (1.0f / 3.0f);
        r += (g_tokfc[b * 3] + g_tokfc[b * 3 + 1] + g_tokfc[b * 3 + 2]) * (1.0f / 3.0f);
        out[b] = r + bfc[0];
    }
}

// ---------- launch ----------
extern "C" void kernel_launch(void* const* d_in, const int* in_sizes, int n_in,
                              void* d_out, int out_size) {
    (void)in_sizes; (void)n_in; (void)out_size;
    const float* x    = (const float*)d_in[0];
    const int*   sidx = (const int*)d_in[1];
    const int*   rot  = (const int*)d_in[2];
    const int*   fh   = (const int*)d_in[3];
    const int*   fw   = (const int*)d_in[4];
    const float* W_pe = (const float*)d_in[5];
    const float* pos  = (const float*)d_in[6];
    const float* ln_g = (const float*)d_in[7];
    const float* ln_b = (const float*)d_in[8];
    const float* W_no = (const float*)d_in[9];
    const float* Wq   = (const float*)d_in[10];
    const float* Wk   = (const float*)d_in[11];
    const float* Wv   = (const float*)d_in[12];
    const float* Wo   = (const float*)d_in[13];
    const float* ah_g = (const float*)d_in[14];
    const float* ah_b = (const float*)d_in[15];
    const float* W_fc = (const float*)d_in[16];
    const float* b_fc = (const float*)d_in[17];
    float* out = (float*)d_out;

    static cudaStream_t s2 = nullptr;
    static cudaEvent_t e_fork = nullptr, e_join = nullptr;
    if (s2 == nullptr) {
        cudaStreamCreateWithFlags(&s2, cudaStreamNonBlocking);
        cudaEventCreateWithFlags(&e_fork, cudaEventDisableTiming);
        cudaEventCreateWithFlags(&e_join, cudaEventDisableTiming);
    }

    cudaFuncSetAttribute(k_planes, cudaFuncAttributeMaxDynamicSharedMemorySize, 217088);

    // fork: k_setup runs concurrently with planes + gemm_bn
    cudaEventRecord(e_fork, 0);
    cudaStreamWaitEvent(s2, e_fork, 0);
    k_setup<<<4360, 256, 0, s2>>>(pos, Wo, W_fc);
    cudaEventRecord(e_join, s2);

    k_planes<<<192, 1024, 216832>>>(x, sidx, rot, fh, fw);
    k_gemm_bn<<<dim3(8, 1, 66), 256>>>(W_pe, W_no);

    // join: reduce_bn needs g_mpart/g_wofc; DCT needs g_Mt
    cudaStreamWaitEvent(0, e_join, 0);

    k_reduce_bn<<<640, 256>>>(ln_g, ln_b, Wv);
    k_gemm<<<dim3(8, 8, 3), 256>>>(3, W_pe, W_pe, 1, 1024, 8, 3);    // DCT, S=8
    k_ln_tokens<<<192, 256>>>(ah_g, ah_b, W_fc);
    k_gemm<<<dim3(8, 8, 6), 256>>>(4, Wq, Wk, 0, 1024, 8, 3);        // q,k
    k_final<<<64, 1024>>>(b_fc, out);
}